// round 13
// baseline (speedup 1.0000x reference)
#include <cuda_runtime.h>
#include <cuda_bf16.h>
#include <cstdint>

#define D 64
#define NUM_REL 32
#define MAXB 131072
#define GROUP 128
#define MAX_GROUPS (MAXB / GROUP + NUM_REL)   // 1056
#define THREADS 256

// dynamic smem layout (bytes)
#define SM_IDX  0                      // 128 ints
#define SM_AHI  1024                   // 128 rows x 128 B (bf16 hi)   16 KB
#define SM_ALO  (SM_AHI + 16384)       // 16 KB
#define SM_BHI  (SM_ALO + 16384)       // 64 rows x 128 B               8 KB
#define SM_BLO  (SM_BHI + 8192)        // 8 KB  (contiguous after BHI)
#define SMEM_TOTAL (SM_BLO + 8192)     // 50176 B

// Scratch (static device globals — zero-initialized at module load)
__device__ int g_counts[NUM_REL];
__device__ int g_n[NUM_REL];
__device__ int g_table[MAX_GROUPS];
__device__ int g_idx[NUM_REL * MAXB];
__device__ int g_done;
// pre-split, pre-swizzled B smem image per relation:
// 1024 uint4 per relation = [hi: 0..511 | lo: 512..1023]
__device__ uint4 g_Bimg[NUM_REL * 1024];

// ---------------------------------------------------------------------------
// helpers
// ---------------------------------------------------------------------------
__device__ __forceinline__ uint32_t smem_u32(const void* p) {
    uint32_t a;
    asm("{ .reg .u64 t; cvta.to.shared.u64 t, %1; cvt.u32.u64 %0, t; }"
        : "=r"(a) : "l"(p));
    return a;
}
// fp32 pair -> bf16x2 (hi) + bf16x2 (lo residual); low half = first element
__device__ __forceinline__ void split2(float x0, float x1, uint32_t& hi, uint32_t& lo) {
    __nv_bfloat162 hv = __floats2bfloat162_rn(x0, x1);
    __nv_bfloat162 lv = __floats2bfloat162_rn(x0 - __bfloat162float(hv.x),
                                              x1 - __bfloat162float(hv.y));
    hi = *reinterpret_cast<uint32_t*>(&hv);
    lo = *reinterpret_cast<uint32_t*>(&lv);
}
__device__ __forceinline__ void ldsm_x4(uint32_t addr, uint32_t& r0, uint32_t& r1,
                                        uint32_t& r2, uint32_t& r3) {
    asm volatile("ldmatrix.sync.aligned.m8n8.x4.shared.b16 {%0,%1,%2,%3}, [%4];"
                 : "=r"(r0), "=r"(r1), "=r"(r2), "=r"(r3) : "r"(addr));
}
// D(fp32) += A(bf16 m16k16) * B(bf16 k16n8)
__device__ __forceinline__ void mma_bf16(float* c, const uint32_t* a,
                                         uint32_t b0, uint32_t b1) {
    asm volatile(
        "mma.sync.aligned.m16n8k16.row.col.f32.bf16.bf16.f32 "
        "{%0,%1,%2,%3}, {%4,%5,%6,%7}, {%8,%9}, {%0,%1,%2,%3};"
        : "+f"(c[0]), "+f"(c[1]), "+f"(c[2]), "+f"(c[3])
        : "r"(a[0]), "r"(a[1]), "r"(a[2]), "r"(a[3]), "r"(b0), "r"(b1));
}
__device__ __forceinline__ void prefetch_l2(const void* p) {
    asm volatile("prefetch.global.L2 [%0];" :: "l"(p));
}

// ---------------------------------------------------------------------------
// Kernel 1: bucket + prep + fused plan (unchanged; proven rounds 10-12)
// ---------------------------------------------------------------------------
__global__ void __launch_bounds__(256)
bucket_kernel(const int* __restrict__ rels, const float* __restrict__ relw, int B) {
    __shared__ int   s_count[NUM_REL];
    __shared__ int   s_base[NUM_REL];
    __shared__ int   s_last;
    __shared__ __align__(16) float Rtmp[D * D];

    const int t     = threadIdx.x;
    const int lane  = t & 31;
    const int nbuck = (int)gridDim.x - NUM_REL;

    if ((int)blockIdx.x >= nbuck) {
        const int r = (int)blockIdx.x - nbuck;
        {
            const float4* src = reinterpret_cast<const float4*>(relw + r * (D * D));
            float4* dst = reinterpret_cast<float4*>(Rtmp);
            #pragma unroll
            for (int i = t; i < (D * D) / 4; i += 256) dst[i] = src[i];
        }
        __syncthreads();
        {
            const int n = t & 63;
            const int cbase = (t >> 6) * 2;
            #pragma unroll
            for (int j = 0; j < 2; j++) {
                const int c = cbase + j;
                uint32_t hi[4], lo[4];
                #pragma unroll
                for (int q = 0; q < 4; q++) {
                    const int k = c * 8 + q * 2;
                    split2(Rtmp[k * D + n], Rtmp[(k + 1) * D + n], hi[q], lo[q]);
                }
                const int e = n * 8 + (c ^ (n & 7));
                g_Bimg[r * 1024 + e]       = make_uint4(hi[0], hi[1], hi[2], hi[3]);
                g_Bimg[r * 1024 + 512 + e] = make_uint4(lo[0], lo[1], lo[2], lo[3]);
            }
        }
    } else {
        if (t < NUM_REL) s_count[t] = 0;
        __syncthreads();

        const int i = blockIdx.x * 256 + t;
        int r = 0, lp = 0;
        const bool valid = (i < B);
        if (valid) r = rels[i];
        {
            unsigned am = __ballot_sync(0xffffffffu, valid);
            if (valid) {
                unsigned mask   = __match_any_sync(am, r);
                int      leader = __ffs(mask) - 1;
                int      rank   = __popc(mask & ((1u << lane) - 1));
                int      base   = 0;
                if (lane == leader) base = atomicAdd(&s_count[r], __popc(mask));
                base = __shfl_sync(am, base, leader);
                lp = base + rank;
            }
        }
        __syncthreads();
        if (t < NUM_REL) s_base[t] = atomicAdd(&g_counts[t], s_count[t]);
        __syncthreads();
        if (valid) g_idx[r * MAXB + s_base[r] + lp] = i;
    }

    __threadfence();
    __syncthreads();
    if (t == 0) {
        int ticket = atomicAdd(&g_done, 1);
        s_last = (ticket == (int)gridDim.x - 1);
    }
    __syncthreads();
    if (s_last && t < 32) {
        int n = atomicAdd(&g_counts[t], 0);
        g_n[t] = n;
        g_counts[t] = 0;
        int ng = (n + GROUP - 1) / GROUP;
        int s = ng;
        #pragma unroll
        for (int o = 1; o < 32; o <<= 1) {
            int v = __shfl_up_sync(0xffffffffu, s, o);
            if (t >= o) s += v;
        }
        int start = s - ng;
        int total = __shfl_sync(0xffffffffu, s, 31);
        for (int g = 0; g < ng; g++) g_table[start + g] = t | (g << 8);
        for (int j = total + t; j < MAX_GROUPS; j += 32) g_table[j] = -1;
        if (t == 0) g_done = 0;
    }
}

// ---------------------------------------------------------------------------
// Kernel 2: score via mma.sync bf16 2-term split.
// Block = 128 samples of one relation, now 8 WARPS: warp w owns m-rows
// [16w, 16w+16). 2 threads cooperate per A row; e2 rows L2-prefetched at
// start; single __syncthreads before the mainloop.
// ---------------------------------------------------------------------------
__global__ void __launch_bounds__(THREADS, 3)
score_kernel(const float* __restrict__ e1g,
             const float* __restrict__ e2g,
             float* __restrict__ out)
{
    extern __shared__ __align__(1024) char smem[];
    const uint32_t sb = smem_u32(smem);
    int* s_idx = reinterpret_cast<int*>(smem + SM_IDX);

    const int item = g_table[blockIdx.x];
    if (item < 0) return;
    const int r    = item & 255;
    const int grp  = item >> 8;
    const int cnt0 = g_n[r] - grp * GROUP;
    const int cnt  = cnt0 < GROUP ? cnt0 : GROUP;
    const int* __restrict__ idx = g_idx + r * MAXB + grp * GROUP;

    const int t = threadIdx.x;

    // this thread's A row (2 threads per row)
    const int m  = t >> 1;
    const int hf = t & 1;
    const int b  = idx[m < cnt ? m : cnt - 1];
    if (hf == 0) s_idx[m] = b;
    // prefetch this sample's e2 row into L2 (2 x 128B lines, one per thread)
    prefetch_l2(reinterpret_cast<const char*>(e2g + b * D) + hf * 128);

    // ---- B staging: copy pre-split swizzled image (1024 uint4 = 16 KB) ----
    {
        const uint4* src = g_Bimg + r * 1024;
        uint4* dst = reinterpret_cast<uint4*>(smem + SM_BHI);
        #pragma unroll
        for (int it = 0; it < 4; it++) dst[t + it * THREADS] = src[t + it * THREADS];
    }

    // ---- A staging: 2 threads per row; this thread does chunks hf*4..hf*4+3
    {
        const float4* p1 = reinterpret_cast<const float4*>(e1g) + b * (D / 4);
        #pragma unroll
        for (int j = 0; j < 4; j++) {
            const int c = hf * 4 + j;              // chunk c: k = 8c..8c+7
            float4 f0 = p1[2 * c];
            float4 f1 = p1[2 * c + 1];
            uint32_t h0, l0, h1, l1, h2, l2, h3, l3;
            split2(f0.x, f0.y, h0, l0);
            split2(f0.z, f0.w, h1, l1);
            split2(f1.x, f1.y, h2, l2);
            split2(f1.z, f1.w, h3, l3);
            const uint32_t off = (uint32_t)(m * 128 + ((c ^ (m & 7)) << 4));
            *reinterpret_cast<uint4*>(smem + SM_AHI + off) = make_uint4(h0, h1, h2, h3);
            *reinterpret_cast<uint4*>(smem + SM_ALO + off) = make_uint4(l0, l1, l2, l3);
        }
    }
    __syncthreads();

    // ---- MMA mainloop: warp w owns m16 tile at rows 16w ----
    const int lane = t & 31;
    const int w    = t >> 5;

    float acc[8][4];
    #pragma unroll
    for (int nt = 0; nt < 8; nt++)
        #pragma unroll
        for (int q = 0; q < 4; q++) acc[nt][q] = 0.0f;

    #pragma unroll
    for (int ks = 0; ks < 4; ks++) {
        uint32_t ah[4], al[4];
        {
            const int row   = 16 * w + (lane & 15);
            const int chunk = 2 * ks + (lane >> 4);
            const uint32_t off =
                (uint32_t)(row * 128 + ((chunk ^ (row & 7)) << 4));
            ldsm_x4(sb + SM_AHI + off, ah[0], ah[1], ah[2], ah[3]);
            ldsm_x4(sb + SM_ALO + off, al[0], al[1], al[2], al[3]);
        }
        uint32_t bh[8][2], bl[8][2];
        #pragma unroll
        for (int p = 0; p < 4; p++) {
            const int n     = 16 * p + ((lane >> 4) << 3) + (lane & 7);
            const int chunk = 2 * ks + ((lane >> 3) & 1);
            const uint32_t off =
                (uint32_t)(n * 128 + ((chunk ^ (n & 7)) << 4));
            ldsm_x4(sb + SM_BHI + off, bh[2 * p][0], bh[2 * p][1],
                                        bh[2 * p + 1][0], bh[2 * p + 1][1]);
            ldsm_x4(sb + SM_BLO + off, bl[2 * p][0], bl[2 * p][1],
                                        bl[2 * p + 1][0], bl[2 * p + 1][1]);
        }
        #pragma unroll
        for (int nt = 0; nt < 8; nt++) {
            mma_bf16(acc[nt], ah, bh[nt][0], bh[nt][1]);
            mma_bf16(acc[nt], ah, bl[nt][0], bl[nt][1]);
            mma_bf16(acc[nt], al, bh[nt][0], bh[nt][1]);
        }
    }

    // ---- epilogue: dot c-fragments with e2, quad-reduce, store ----
    {
        const int g  = lane >> 2;
        const int tg = lane & 3;
        #pragma unroll
        for (int v = 0; v < 2; v++) {
            const int mr = 16 * w + g + 8 * v;
            const int bm = s_idx[mr];
            float p = 0.0f;
            #pragma unroll
            for (int nt = 0; nt < 8; nt++) {
                const float2 u = *reinterpret_cast<const float2*>(
                    e2g + bm * D + nt * 8 + 2 * tg);
                p += acc[nt][2 * v]     * u.x;
                p += acc[nt][2 * v + 1] * u.y;
            }
            p += __shfl_xor_sync(0xffffffffu, p, 1);
            p += __shfl_xor_sync(0xffffffffu, p, 2);
            if (tg == 0 && mr < cnt) out[bm] = p;
        }
    }
}

// ---------------------------------------------------------------------------
// kernel_launch
// inputs: embeds1 [B*64] f32, embeds2 [B*64] f32, rels [B] i32,
//         rel_embeds [32*4096] f32 ; output [B] f32
// ---------------------------------------------------------------------------
extern "C" void kernel_launch(void* const* d_in, const int* in_sizes, int n_in,
                              void* d_out, int out_size) {
    const float* e1   = (const float*)d_in[0];
    const float* e2   = (const float*)d_in[1];
    const int*   rels = (const int*)d_in[2];
    const float* relw = (const float*)d_in[3];
    float* out = (float*)d_out;

    const int B = in_sizes[2];
    const int NB = (B + 255) / 256;

    cudaFuncSetAttribute(score_kernel,
                         cudaFuncAttributeMaxDynamicSharedMemorySize, SMEM_TOTAL);

    bucket_kernel<<<NB + NUM_REL, 256>>>(rels, relw, B);
    score_kernel<<<MAX_GROUPS, THREADS, SMEM_TOTAL>>>(e1, e2, out);
}

// round 14
// speedup vs baseline: 1.0606x; 1.0606x over previous
#include <cuda_runtime.h>
#include <cuda_bf16.h>
#include <cstdint>

#define D 64
#define NUM_REL 32
#define MAXB 131072
#define GROUP 128
#define MAX_GROUPS (MAXB / GROUP + NUM_REL)   // 1056
#define THREADS 128

// dynamic smem layout (bytes)
#define SM_IDX0 0                      // 128 ints
#define SM_IDX1 512                    // 128 ints
#define SM_AHI  1024                   // 128 rows x 128 B (bf16 hi)   16 KB
#define SM_ALO  (SM_AHI + 16384)       // 16 KB
#define SM_BHI  (SM_ALO + 16384)       // 64 rows x 128 B               8 KB
#define SM_BLO  (SM_BHI + 8192)        // 8 KB  (contiguous after BHI)
#define SMEM_TOTAL (SM_BLO + 8192)     // 50176 B

// Scratch (static device globals — zero-initialized at module load)
__device__ int g_counts[NUM_REL];
__device__ int g_n[NUM_REL];
__device__ int g_table[MAX_GROUPS];
__device__ int g_idx[NUM_REL * MAXB];
__device__ int g_done;
// pre-split, pre-swizzled B smem image per relation:
// 1024 uint4 per relation = [hi: 0..511 | lo: 512..1023]
__device__ uint4 g_Bimg[NUM_REL * 1024];

// ---------------------------------------------------------------------------
// helpers
// ---------------------------------------------------------------------------
__device__ __forceinline__ uint32_t smem_u32(const void* p) {
    uint32_t a;
    asm("{ .reg .u64 t; cvta.to.shared.u64 t, %1; cvt.u32.u64 %0, t; }"
        : "=r"(a) : "l"(p));
    return a;
}
__device__ __forceinline__ void split2(float x0, float x1, uint32_t& hi, uint32_t& lo) {
    __nv_bfloat162 hv = __floats2bfloat162_rn(x0, x1);
    __nv_bfloat162 lv = __floats2bfloat162_rn(x0 - __bfloat162float(hv.x),
                                              x1 - __bfloat162float(hv.y));
    hi = *reinterpret_cast<uint32_t*>(&hv);
    lo = *reinterpret_cast<uint32_t*>(&lv);
}
__device__ __forceinline__ void ldsm_x4(uint32_t addr, uint32_t& r0, uint32_t& r1,
                                        uint32_t& r2, uint32_t& r3) {
    asm volatile("ldmatrix.sync.aligned.m8n8.x4.shared.b16 {%0,%1,%2,%3}, [%4];"
                 : "=r"(r0), "=r"(r1), "=r"(r2), "=r"(r3) : "r"(addr));
}
__device__ __forceinline__ void mma_bf16(float* c, const uint32_t* a,
                                         uint32_t b0, uint32_t b1) {
    asm volatile(
        "mma.sync.aligned.m16n8k16.row.col.f32.bf16.bf16.f32 "
        "{%0,%1,%2,%3}, {%4,%5,%6,%7}, {%8,%9}, {%0,%1,%2,%3};"
        : "+f"(c[0]), "+f"(c[1]), "+f"(c[2]), "+f"(c[3])
        : "r"(a[0]), "r"(a[1]), "r"(a[2]), "r"(a[3]), "r"(b0), "r"(b1));
}
__device__ __forceinline__ void prefetch_l2(const void* p) {
    asm volatile("prefetch.global.L2 [%0];" :: "l"(p));
}

// ---------------------------------------------------------------------------
// Kernel 1: bucket + prep + fused plan (unchanged; proven rounds 10-12)
// ---------------------------------------------------------------------------
__global__ void __launch_bounds__(256)
bucket_kernel(const int* __restrict__ rels, const float* __restrict__ relw, int B) {
    __shared__ int   s_count[NUM_REL];
    __shared__ int   s_base[NUM_REL];
    __shared__ int   s_last;
    __shared__ __align__(16) float Rtmp[D * D];

    const int t     = threadIdx.x;
    const int lane  = t & 31;
    const int nbuck = (int)gridDim.x - NUM_REL;

    if ((int)blockIdx.x >= nbuck) {
        const int r = (int)blockIdx.x - nbuck;
        {
            const float4* src = reinterpret_cast<const float4*>(relw + r * (D * D));
            float4* dst = reinterpret_cast<float4*>(Rtmp);
            #pragma unroll
            for (int i = t; i < (D * D) / 4; i += 256) dst[i] = src[i];
        }
        __syncthreads();
        {
            const int n = t & 63;
            const int cbase = (t >> 6) * 2;
            #pragma unroll
            for (int j = 0; j < 2; j++) {
                const int c = cbase + j;
                uint32_t hi[4], lo[4];
                #pragma unroll
                for (int q = 0; q < 4; q++) {
                    const int k = c * 8 + q * 2;
                    split2(Rtmp[k * D + n], Rtmp[(k + 1) * D + n], hi[q], lo[q]);
                }
                const int e = n * 8 + (c ^ (n & 7));
                g_Bimg[r * 1024 + e]       = make_uint4(hi[0], hi[1], hi[2], hi[3]);
                g_Bimg[r * 1024 + 512 + e] = make_uint4(lo[0], lo[1], lo[2], lo[3]);
            }
        }
    } else {
        if (t < NUM_REL) s_count[t] = 0;
        __syncthreads();

        const int i = blockIdx.x * 256 + t;
        int r = 0, lp = 0;
        const bool valid = (i < B);
        if (valid) r = rels[i];
        {
            unsigned am = __ballot_sync(0xffffffffu, valid);
            if (valid) {
                unsigned mask   = __match_any_sync(am, r);
                int      leader = __ffs(mask) - 1;
                int      rank   = __popc(mask & ((1u << lane) - 1));
                int      base   = 0;
                if (lane == leader) base = atomicAdd(&s_count[r], __popc(mask));
                base = __shfl_sync(am, base, leader);
                lp = base + rank;
            }
        }
        __syncthreads();
        if (t < NUM_REL) s_base[t] = atomicAdd(&g_counts[t], s_count[t]);
        __syncthreads();
        if (valid) g_idx[r * MAXB + s_base[r] + lp] = i;
    }

    __threadfence();
    __syncthreads();
    if (t == 0) {
        int ticket = atomicAdd(&g_done, 1);
        s_last = (ticket == (int)gridDim.x - 1);
    }
    __syncthreads();
    if (s_last && t < 32) {
        int n = atomicAdd(&g_counts[t], 0);
        g_n[t] = n;
        g_counts[t] = 0;
        int ng = (n + GROUP - 1) / GROUP;
        int s = ng;
        #pragma unroll
        for (int o = 1; o < 32; o <<= 1) {
            int v = __shfl_up_sync(0xffffffffu, s, o);
            if (t >= o) s += v;
        }
        int start = s - ng;
        int total = __shfl_sync(0xffffffffu, s, 31);
        for (int g = 0; g < ng; g++) g_table[start + g] = t | (g << 8);
        for (int j = total + t; j < MAX_GROUPS; j += 32) g_table[j] = -1;
        if (t == 0) g_done = 0;
    }
}

// ---------------------------------------------------------------------------
// score building blocks (byte-identical round-12 core)
// ---------------------------------------------------------------------------
__device__ __forceinline__ void copy_B(char* smem, int r, int t) {
    const uint4* src = g_Bimg + r * 1024;
    uint4* dst = reinterpret_cast<uint4*>(smem + SM_BHI);
    #pragma unroll
    for (int it = 0; it < 8; it++) dst[t + it * THREADS] = src[t + it * THREADS];
}

__device__ __forceinline__ void stage_A(char* smem, const float* __restrict__ e1g,
                                        int b, int m) {
    const float4* p1 = reinterpret_cast<const float4*>(e1g) + b * (D / 4);
    #pragma unroll
    for (int c = 0; c < 8; c++) {              // chunk c: k = 8c..8c+7
        float4 f0 = p1[2 * c];
        float4 f1 = p1[2 * c + 1];
        uint32_t h0, l0, h1, l1, h2, l2, h3, l3;
        split2(f0.x, f0.y, h0, l0);
        split2(f0.z, f0.w, h1, l1);
        split2(f1.x, f1.y, h2, l2);
        split2(f1.z, f1.w, h3, l3);
        const uint32_t off = (uint32_t)(m * 128 + ((c ^ (m & 7)) << 4));
        *reinterpret_cast<uint4*>(smem + SM_AHI + off) = make_uint4(h0, h1, h2, h3);
        *reinterpret_cast<uint4*>(smem + SM_ALO + off) = make_uint4(l0, l1, l2, l3);
    }
}

// MMA mainloop + epilogue for the currently staged group.
__device__ __forceinline__ void run_group(uint32_t sb,
                                          const float* __restrict__ e2g,
                                          float* __restrict__ out,
                                          const int* __restrict__ s_idx,
                                          int cnt, int t) {
    const int lane = t & 31;
    const int w    = t >> 5;

    float acc[2][8][4];
    #pragma unroll
    for (int mt = 0; mt < 2; mt++)
        #pragma unroll
        for (int nt = 0; nt < 8; nt++)
            #pragma unroll
            for (int q = 0; q < 4; q++) acc[mt][nt][q] = 0.0f;

    #pragma unroll
    for (int ks = 0; ks < 4; ks++) {
        uint32_t ah[2][4], al[2][4];
        #pragma unroll
        for (int mt = 0; mt < 2; mt++) {
            const int row   = 32 * w + 16 * mt + (lane & 15);
            const int chunk = 2 * ks + (lane >> 4);
            const uint32_t off =
                (uint32_t)(row * 128 + ((chunk ^ (row & 7)) << 4));
            ldsm_x4(sb + SM_AHI + off, ah[mt][0], ah[mt][1], ah[mt][2], ah[mt][3]);
            ldsm_x4(sb + SM_ALO + off, al[mt][0], al[mt][1], al[mt][2], al[mt][3]);
        }
        uint32_t bh[8][2], bl[8][2];
        #pragma unroll
        for (int p = 0; p < 4; p++) {
            const int n     = 16 * p + ((lane >> 4) << 3) + (lane & 7);
            const int chunk = 2 * ks + ((lane >> 3) & 1);
            const uint32_t off =
                (uint32_t)(n * 128 + ((chunk ^ (n & 7)) << 4));
            ldsm_x4(sb + SM_BHI + off, bh[2 * p][0], bh[2 * p][1],
                                        bh[2 * p + 1][0], bh[2 * p + 1][1]);
            ldsm_x4(sb + SM_BLO + off, bl[2 * p][0], bl[2 * p][1],
                                        bl[2 * p + 1][0], bl[2 * p + 1][1]);
        }
        #pragma unroll
        for (int mt = 0; mt < 2; mt++)
            #pragma unroll
            for (int nt = 0; nt < 8; nt++) {
                mma_bf16(acc[mt][nt], ah[mt], bh[nt][0], bh[nt][1]);
                mma_bf16(acc[mt][nt], ah[mt], bl[nt][0], bl[nt][1]);
                mma_bf16(acc[mt][nt], al[mt], bh[nt][0], bh[nt][1]);
            }
    }

    const int g  = lane >> 2;
    const int tg = lane & 3;
    #pragma unroll
    for (int mt = 0; mt < 2; mt++) {
        #pragma unroll
        for (int v = 0; v < 2; v++) {
            const int m  = 32 * w + 16 * mt + g + 8 * v;
            const int bm = s_idx[m];
            float p = 0.0f;
            #pragma unroll
            for (int nt = 0; nt < 8; nt++) {
                const float2 u = *reinterpret_cast<const float2*>(
                    e2g + bm * D + nt * 8 + 2 * tg);
                p += acc[mt][nt][2 * v]     * u.x;
                p += acc[mt][nt][2 * v + 1] * u.y;
            }
            p += __shfl_xor_sync(0xffffffffu, p, 1);
            p += __shfl_xor_sync(0xffffffffu, p, 2);
            if (tg == 0 && m < cnt) out[bm] = p;
        }
    }
}

// ---------------------------------------------------------------------------
// Kernel 2: score — paired-group persistent blocks.
// Block b processes groups 2b and 2b+1 (same relation ~94% of the time ->
// B copy reused). Group 2's e1/e2 rows are L2-prefetched at block start so
// its staging hits warm L2 after group 1's MMA.
// ---------------------------------------------------------------------------
__global__ void __launch_bounds__(THREADS, 4)
score_kernel(const float* __restrict__ e1g,
             const float* __restrict__ e2g,
             float* __restrict__ out)
{
    extern __shared__ __align__(1024) char smem[];
    const uint32_t sb = smem_u32(smem);
    int* s_idx0 = reinterpret_cast<int*>(smem + SM_IDX0);
    int* s_idx1 = reinterpret_cast<int*>(smem + SM_IDX1);

    const int g0 = 2 * (int)blockIdx.x;
    const int item0 = g_table[g0];
    if (item0 < 0) return;                    // table is packed: rest is -1 too
    const int item1 = (g0 + 1 < MAX_GROUPS) ? g_table[g0 + 1] : -1;

    const int t = threadIdx.x;

    // group 0 bookkeeping
    const int r0   = item0 & 255;
    const int grp0 = item0 >> 8;
    const int c0   = g_n[r0] - grp0 * GROUP;
    const int cnt0 = c0 < GROUP ? c0 : GROUP;
    const int bA   = g_idx[r0 * MAXB + grp0 * GROUP + (t < cnt0 ? t : cnt0 - 1)];
    s_idx0[t] = bA;

    // group 1 bookkeeping + L2 prefetch of its gather rows
    int r1 = -1, cnt1 = 0;
    if (item1 >= 0) {
        r1 = item1 & 255;
        const int grp1 = item1 >> 8;
        const int c1   = g_n[r1] - grp1 * GROUP;
        cnt1 = c1 < GROUP ? c1 : GROUP;
        const int bB = g_idx[r1 * MAXB + grp1 * GROUP + (t < cnt1 ? t : cnt1 - 1)];
        s_idx1[t] = bB;
        prefetch_l2(e1g + bB * D);
        prefetch_l2(e1g + bB * D + 32);
        prefetch_l2(e2g + bB * D);
        prefetch_l2(e2g + bB * D + 32);
    }
    // group 0 epilogue rows -> L2
    prefetch_l2(e2g + bA * D);
    prefetch_l2(e2g + bA * D + 32);

    // ---- group 0 ----
    copy_B(smem, r0, t);
    stage_A(smem, e1g, bA, t);
    __syncthreads();
    run_group(sb, e2g, out, s_idx0, cnt0, t);

    if (item1 < 0) return;

    // ---- group 1 ----
    __syncthreads();                          // all ldsm/s_idx reads done
    if (r1 != r0) copy_B(smem, r1, t);
    stage_A(smem, e1g, s_idx1[t], t);
    __syncthreads();
    run_group(sb, e2g, out, s_idx1, cnt1, t);
}

// ---------------------------------------------------------------------------
// kernel_launch
// inputs: embeds1 [B*64] f32, embeds2 [B*64] f32, rels [B] i32,
//         rel_embeds [32*4096] f32 ; output [B] f32
// ---------------------------------------------------------------------------
extern "C" void kernel_launch(void* const* d_in, const int* in_sizes, int n_in,
                              void* d_out, int out_size) {
    const float* e1   = (const float*)d_in[0];
    const float* e2   = (const float*)d_in[1];
    const int*   rels = (const int*)d_in[2];
    const float* relw = (const float*)d_in[3];
    float* out = (float*)d_out;

    const int B = in_sizes[2];
    const int NB = (B + 255) / 256;

    cudaFuncSetAttribute(score_kernel,
                         cudaFuncAttributeMaxDynamicSharedMemorySize, SMEM_TOTAL);

    bucket_kernel<<<NB + NUM_REL, 256>>>(rels, relw, B);
    score_kernel<<<(MAX_GROUPS + 1) / 2, THREADS, SMEM_TOTAL>>>(e1, e2, out);
}

// round 15
// speedup vs baseline: 1.0814x; 1.0196x over previous
#include <cuda_runtime.h>
#include <cuda_bf16.h>
#include <cstdint>

#define D 64
#define NUM_REL 32
#define MAXB 131072
#define GROUP 128
#define MAX_GROUPS (MAXB / GROUP + NUM_REL)   // 1056
#define THREADS 128

// dynamic smem layout (bytes)
#define SM_IDX  0                      // 128 ints
#define SM_AHI  1024                   // 128 rows x 128 B (bf16 hi)   16 KB
#define SM_ALO  (SM_AHI + 16384)       // 16 KB
#define SM_BHI  (SM_ALO + 16384)       // 64 rows x 128 B               8 KB
#define SM_BLO  (SM_BHI + 8192)        // 8 KB  (contiguous after BHI)
#define SMEM_TOTAL (SM_BLO + 8192)     // 50176 B

// Scratch (static device globals — zero-initialized at module load)
__device__ int g_counts[NUM_REL];
__device__ int g_n[NUM_REL];
__device__ int g_table[MAX_GROUPS];
__device__ int g_idx[NUM_REL * MAXB];
__device__ int g_done;
// pre-split, pre-swizzled B smem image per relation:
// 1024 uint4 per relation = [hi: 0..511 | lo: 512..1023]
__device__ uint4 g_Bimg[NUM_REL * 1024];

// ---------------------------------------------------------------------------
// helpers
// ---------------------------------------------------------------------------
__device__ __forceinline__ uint32_t smem_u32(const void* p) {
    uint32_t a;
    asm("{ .reg .u64 t; cvta.to.shared.u64 t, %1; cvt.u32.u64 %0, t; }"
        : "=r"(a) : "l"(p));
    return a;
}
__device__ __forceinline__ void split2(float x0, float x1, uint32_t& hi, uint32_t& lo) {
    __nv_bfloat162 hv = __floats2bfloat162_rn(x0, x1);
    __nv_bfloat162 lv = __floats2bfloat162_rn(x0 - __bfloat162float(hv.x),
                                              x1 - __bfloat162float(hv.y));
    hi = *reinterpret_cast<uint32_t*>(&hv);
    lo = *reinterpret_cast<uint32_t*>(&lv);
}
__device__ __forceinline__ void ldsm_x4(uint32_t addr, uint32_t& r0, uint32_t& r1,
                                        uint32_t& r2, uint32_t& r3) {
    asm volatile("ldmatrix.sync.aligned.m8n8.x4.shared.b16 {%0,%1,%2,%3}, [%4];"
                 : "=r"(r0), "=r"(r1), "=r"(r2), "=r"(r3) : "r"(addr));
}
__device__ __forceinline__ void mma_bf16(float* c, const uint32_t* a,
                                         uint32_t b0, uint32_t b1) {
    asm volatile(
        "mma.sync.aligned.m16n8k16.row.col.f32.bf16.bf16.f32 "
        "{%0,%1,%2,%3}, {%4,%5,%6,%7}, {%8,%9}, {%0,%1,%2,%3};"
        : "+f"(c[0]), "+f"(c[1]), "+f"(c[2]), "+f"(c[3])
        : "r"(a[0]), "r"(a[1]), "r"(a[2]), "r"(a[3]), "r"(b0), "r"(b1));
}
__device__ __forceinline__ void prefetch_l2(const void* p) {
    asm volatile("prefetch.global.L2 [%0];" :: "l"(p));
}
// 16B global -> shared async copy (sm_80+ LDGSTS)
__device__ __forceinline__ void cp_async16(uint32_t smem_addr, const void* gmem) {
    asm volatile("cp.async.cg.shared.global [%0], [%1], 16;"
                 :: "r"(smem_addr), "l"(gmem) : "memory");
}
__device__ __forceinline__ void cp_async_commit_wait() {
    asm volatile("cp.async.commit_group;\n\tcp.async.wait_group 0;" ::: "memory");
}

// ---------------------------------------------------------------------------
// Kernel 1: bucket + prep + fused plan (unchanged; proven rounds 10-14)
// ---------------------------------------------------------------------------
__global__ void __launch_bounds__(256)
bucket_kernel(const int* __restrict__ rels, const float* __restrict__ relw, int B) {
    __shared__ int   s_count[NUM_REL];
    __shared__ int   s_base[NUM_REL];
    __shared__ int   s_last;
    __shared__ __align__(16) float Rtmp[D * D];

    const int t     = threadIdx.x;
    const int lane  = t & 31;
    const int nbuck = (int)gridDim.x - NUM_REL;

    if ((int)blockIdx.x >= nbuck) {
        const int r = (int)blockIdx.x - nbuck;
        {
            const float4* src = reinterpret_cast<const float4*>(relw + r * (D * D));
            float4* dst = reinterpret_cast<float4*>(Rtmp);
            #pragma unroll
            for (int i = t; i < (D * D) / 4; i += 256) dst[i] = src[i];
        }
        __syncthreads();
        {
            const int n = t & 63;
            const int cbase = (t >> 6) * 2;
            #pragma unroll
            for (int j = 0; j < 2; j++) {
                const int c = cbase + j;
                uint32_t hi[4], lo[4];
                #pragma unroll
                for (int q = 0; q < 4; q++) {
                    const int k = c * 8 + q * 2;
                    split2(Rtmp[k * D + n], Rtmp[(k + 1) * D + n], hi[q], lo[q]);
                }
                const int e = n * 8 + (c ^ (n & 7));
                g_Bimg[r * 1024 + e]       = make_uint4(hi[0], hi[1], hi[2], hi[3]);
                g_Bimg[r * 1024 + 512 + e] = make_uint4(lo[0], lo[1], lo[2], lo[3]);
            }
        }
    } else {
        if (t < NUM_REL) s_count[t] = 0;
        __syncthreads();

        const int i = blockIdx.x * 256 + t;
        int r = 0, lp = 0;
        const bool valid = (i < B);
        if (valid) r = rels[i];
        {
            unsigned am = __ballot_sync(0xffffffffu, valid);
            if (valid) {
                unsigned mask   = __match_any_sync(am, r);
                int      leader = __ffs(mask) - 1;
                int      rank   = __popc(mask & ((1u << lane) - 1));
                int      base   = 0;
                if (lane == leader) base = atomicAdd(&s_count[r], __popc(mask));
                base = __shfl_sync(am, base, leader);
                lp = base + rank;
            }
        }
        __syncthreads();
        if (t < NUM_REL) s_base[t] = atomicAdd(&g_counts[t], s_count[t]);
        __syncthreads();
        if (valid) g_idx[r * MAXB + s_base[r] + lp] = i;
    }

    __threadfence();
    __syncthreads();
    if (t == 0) {
        int ticket = atomicAdd(&g_done, 1);
        s_last = (ticket == (int)gridDim.x - 1);
    }
    __syncthreads();
    if (s_last && t < 32) {
        int n = atomicAdd(&g_counts[t], 0);
        g_n[t] = n;
        g_counts[t] = 0;
        int ng = (n + GROUP - 1) / GROUP;
        int s = ng;
        #pragma unroll
        for (int o = 1; o < 32; o <<= 1) {
            int v = __shfl_up_sync(0xffffffffu, s, o);
            if (t >= o) s += v;
        }
        int start = s - ng;
        int total = __shfl_sync(0xffffffffu, s, 31);
        for (int g = 0; g < ng; g++) g_table[start + g] = t | (g << 8);
        for (int j = total + t; j < MAX_GROUPS; j += 32) g_table[j] = -1;
        if (t == 0) g_done = 0;
    }
}

// ---------------------------------------------------------------------------
// Kernel 2: score (R12 shape: 1056 blocks x 128 thr, 1 group each) with
// overlapped staging: e1 LDGs issued first into registers, B copied via
// cp.async in the background, e2 row L2-prefetched, then split+store, one
// sync, then the verified MMA mainloop + epilogue.
// ---------------------------------------------------------------------------
__global__ void __launch_bounds__(THREADS, 4)
score_kernel(const float* __restrict__ e1g,
             const float* __restrict__ e2g,
             float* __restrict__ out)
{
    extern __shared__ __align__(1024) char smem[];
    const uint32_t sb = smem_u32(smem);
    int* s_idx = reinterpret_cast<int*>(smem + SM_IDX);

    const int item = g_table[blockIdx.x];
    if (item < 0) return;
    const int r    = item & 255;
    const int grp  = item >> 8;
    const int cnt0 = g_n[r] - grp * GROUP;
    const int cnt  = cnt0 < GROUP ? cnt0 : GROUP;
    const int* __restrict__ idx = g_idx + r * MAXB + grp * GROUP;

    const int t = threadIdx.x;
    const int b = idx[t < cnt ? t : cnt - 1];   // this thread's sample row
    s_idx[t] = b;

    // ---- (1) issue all 16 e1 LDG.128s immediately (max MLP) ----
    const float4* p1 = reinterpret_cast<const float4*>(e1g) + b * (D / 4);
    float4 fv[16];
    #pragma unroll
    for (int c = 0; c < 16; c++) fv[c] = p1[c];

    // ---- (2) B copy in the background via cp.async (8 x 16B per thread) ----
    {
        const uint4* src = g_Bimg + r * 1024;
        #pragma unroll
        for (int it = 0; it < 8; it++) {
            const int i = t + it * THREADS;
            cp_async16(sb + SM_BHI + i * 16, src + i);
        }
    }

    // ---- (3) e2 row -> L2 for the epilogue ----
    prefetch_l2(e2g + b * D);
    prefetch_l2(e2g + b * D + 32);

    // ---- split e1 values as they land, swizzled stores ----
    {
        const int m = t;
        #pragma unroll
        for (int c = 0; c < 8; c++) {              // chunk c: k = 8c..8c+7
            float4 f0 = fv[2 * c];
            float4 f1 = fv[2 * c + 1];
            uint32_t h0, l0, h1, l1, h2, l2, h3, l3;
            split2(f0.x, f0.y, h0, l0);
            split2(f0.z, f0.w, h1, l1);
            split2(f1.x, f1.y, h2, l2);
            split2(f1.z, f1.w, h3, l3);
            const uint32_t off = (uint32_t)(m * 128 + ((c ^ (m & 7)) << 4));
            *reinterpret_cast<uint4*>(smem + SM_AHI + off) = make_uint4(h0, h1, h2, h3);
            *reinterpret_cast<uint4*>(smem + SM_ALO + off) = make_uint4(l0, l1, l2, l3);
        }
    }
    cp_async_commit_wait();
    __syncthreads();

    // ---- MMA mainloop (byte-identical to round 12) ----
    const int lane = t & 31;
    const int w    = t >> 5;

    float acc[2][8][4];
    #pragma unroll
    for (int mt = 0; mt < 2; mt++)
        #pragma unroll
        for (int nt = 0; nt < 8; nt++)
            #pragma unroll
            for (int q = 0; q < 4; q++) acc[mt][nt][q] = 0.0f;

    #pragma unroll
    for (int ks = 0; ks < 4; ks++) {
        uint32_t ah[2][4], al[2][4];
        #pragma unroll
        for (int mt = 0; mt < 2; mt++) {
            const int row   = 32 * w + 16 * mt + (lane & 15);
            const int chunk = 2 * ks + (lane >> 4);
            const uint32_t off =
                (uint32_t)(row * 128 + ((chunk ^ (row & 7)) << 4));
            ldsm_x4(sb + SM_AHI + off, ah[mt][0], ah[mt][1], ah[mt][2], ah[mt][3]);
            ldsm_x4(sb + SM_ALO + off, al[mt][0], al[mt][1], al[mt][2], al[mt][3]);
        }
        uint32_t bh[8][2], bl[8][2];
        #pragma unroll
        for (int p = 0; p < 4; p++) {
            const int n     = 16 * p + ((lane >> 4) << 3) + (lane & 7);
            const int chunk = 2 * ks + ((lane >> 3) & 1);
            const uint32_t off =
                (uint32_t)(n * 128 + ((chunk ^ (n & 7)) << 4));
            ldsm_x4(sb + SM_BHI + off, bh[2 * p][0], bh[2 * p][1],
                                        bh[2 * p + 1][0], bh[2 * p + 1][1]);
            ldsm_x4(sb + SM_BLO + off, bl[2 * p][0], bl[2 * p][1],
                                        bl[2 * p + 1][0], bl[2 * p + 1][1]);
        }
        #pragma unroll
        for (int mt = 0; mt < 2; mt++)
            #pragma unroll
            for (int nt = 0; nt < 8; nt++) {
                mma_bf16(acc[mt][nt], ah[mt], bh[nt][0], bh[nt][1]);
                mma_bf16(acc[mt][nt], ah[mt], bl[nt][0], bl[nt][1]);
                mma_bf16(acc[mt][nt], al[mt], bh[nt][0], bh[nt][1]);
            }
    }

    // ---- epilogue: dot c-fragments with e2, quad-reduce, store ----
    {
        const int g  = lane >> 2;
        const int tg = lane & 3;
        #pragma unroll
        for (int mt = 0; mt < 2; mt++) {
            #pragma unroll
            for (int v = 0; v < 2; v++) {
                const int m  = 32 * w + 16 * mt + g + 8 * v;
                const int bm = s_idx[m];
                float p = 0.0f;
                #pragma unroll
                for (int nt = 0; nt < 8; nt++) {
                    const float2 u = *reinterpret_cast<const float2*>(
                        e2g + bm * D + nt * 8 + 2 * tg);
                    p += acc[mt][nt][2 * v]     * u.x;
                    p += acc[mt][nt][2 * v + 1] * u.y;
                }
                p += __shfl_xor_sync(0xffffffffu, p, 1);
                p += __shfl_xor_sync(0xffffffffu, p, 2);
                if (tg == 0 && m < cnt) out[bm] = p;
            }
        }
    }
}

// ---------------------------------------------------------------------------
// kernel_launch
// inputs: embeds1 [B*64] f32, embeds2 [B*64] f32, rels [B] i32,
//         rel_embeds [32*4096] f32 ; output [B] f32
// ---------------------------------------------------------------------------
extern "C" void kernel_launch(void* const* d_in, const int* in_sizes, int n_in,
                              void* d_out, int out_size) {
    const float* e1   = (const float*)d_in[0];
    const float* e2   = (const float*)d_in[1];
    const int*   rels = (const int*)d_in[2];
    const float* relw = (const float*)d_in[3];
    float* out = (float*)d_out;

    const int B = in_sizes[2];
    const int NB = (B + 255) / 256;

    cudaFuncSetAttribute(score_kernel,
                         cudaFuncAttributeMaxDynamicSharedMemorySize, SMEM_TOTAL);

    bucket_kernel<<<NB + NUM_REL, 256>>>(rels, relw, B);
    score_kernel<<<MAX_GROUPS, THREADS, SMEM_TOTAL>>>(e1, e2, out);
}

// round 16
// speedup vs baseline: 1.1209x; 1.0366x over previous
#include <cuda_runtime.h>
#include <cuda_bf16.h>
#include <cstdint>

#define D 64
#define NUM_REL 32
#define MAXB 131072
#define GROUP 128
#define MAX_GROUPS (MAXB / GROUP + NUM_REL)   // 1056
#define THREADS 128

// dynamic smem layout (bytes)
#define SM_IDX  0                      // 128 ints
#define SM_AHI  1024                   // 128 rows x 128 B (bf16 hi)   16 KB
#define SM_ALO  (SM_AHI + 16384)       // 16 KB
#define SM_BHI  (SM_ALO + 16384)       // 64 rows x 128 B               8 KB
#define SM_BLO  (SM_BHI + 8192)        // 8 KB  (contiguous after BHI)
#define SMEM_TOTAL (SM_BLO + 8192)     // 50176 B

// Scratch (static device globals — zero-initialized at module load)
__device__ int g_counts[NUM_REL];
__device__ int g_n[NUM_REL];
__device__ int g_table[MAX_GROUPS];
__device__ int g_idx[NUM_REL * MAXB];
__device__ int g_done;
// pre-split, pre-swizzled B smem image per relation:
// 1024 uint4 per relation = [hi: 0..511 | lo: 512..1023]
__device__ uint4 g_Bimg[NUM_REL * 1024];

// ---------------------------------------------------------------------------
// helpers
// ---------------------------------------------------------------------------
__device__ __forceinline__ uint32_t smem_u32(const void* p) {
    uint32_t a;
    asm("{ .reg .u64 t; cvta.to.shared.u64 t, %1; cvt.u32.u64 %0, t; }"
        : "=r"(a) : "l"(p));
    return a;
}
__device__ __forceinline__ void split2(float x0, float x1, uint32_t& hi, uint32_t& lo) {
    __nv_bfloat162 hv = __floats2bfloat162_rn(x0, x1);
    __nv_bfloat162 lv = __floats2bfloat162_rn(x0 - __bfloat162float(hv.x),
                                              x1 - __bfloat162float(hv.y));
    hi = *reinterpret_cast<uint32_t*>(&hv);
    lo = *reinterpret_cast<uint32_t*>(&lv);
}
__device__ __forceinline__ void ldsm_x4(uint32_t addr, uint32_t& r0, uint32_t& r1,
                                        uint32_t& r2, uint32_t& r3) {
    asm volatile("ldmatrix.sync.aligned.m8n8.x4.shared.b16 {%0,%1,%2,%3}, [%4];"
                 : "=r"(r0), "=r"(r1), "=r"(r2), "=r"(r3) : "r"(addr));
}
__device__ __forceinline__ void mma_bf16(float* c, const uint32_t* a,
                                         uint32_t b0, uint32_t b1) {
    asm volatile(
        "mma.sync.aligned.m16n8k16.row.col.f32.bf16.bf16.f32 "
        "{%0,%1,%2,%3}, {%4,%5,%6,%7}, {%8,%9}, {%0,%1,%2,%3};"
        : "+f"(c[0]), "+f"(c[1]), "+f"(c[2]), "+f"(c[3])
        : "r"(a[0]), "r"(a[1]), "r"(a[2]), "r"(a[3]), "r"(b0), "r"(b1));
}

// ---------------------------------------------------------------------------
// Kernel 1: bucket (int4-vectorized) + prep + fused plan.
// Blocks [0, NB4): each thread buckets 4 samples (one int4 of rels).
// Blocks [NB4, NB4+NUM_REL): build pre-split swizzled B image for a relation.
// Last block to finish (ticket) builds the exact (rel,group) work table.
// ---------------------------------------------------------------------------
__global__ void __launch_bounds__(256)
bucket_kernel(const int* __restrict__ rels, const float* __restrict__ relw, int B) {
    __shared__ int   s_count[NUM_REL];
    __shared__ int   s_base[NUM_REL];
    __shared__ int   s_last;
    __shared__ __align__(16) float Rtmp[D * D];

    const int t     = threadIdx.x;
    const int lane  = t & 31;
    const int nbuck = (int)gridDim.x - NUM_REL;

    if ((int)blockIdx.x >= nbuck) {
        // ---- prep path: relation r ----
        const int r = (int)blockIdx.x - nbuck;
        {
            const float4* src = reinterpret_cast<const float4*>(relw + r * (D * D));
            float4* dst = reinterpret_cast<float4*>(Rtmp);
            #pragma unroll
            for (int i = t; i < (D * D) / 4; i += 256) dst[i] = src[i];
        }
        __syncthreads();
        {
            const int n = t & 63;
            const int cbase = (t >> 6) * 2;
            #pragma unroll
            for (int j = 0; j < 2; j++) {
                const int c = cbase + j;
                uint32_t hi[4], lo[4];
                #pragma unroll
                for (int q = 0; q < 4; q++) {
                    const int k = c * 8 + q * 2;
                    split2(Rtmp[k * D + n], Rtmp[(k + 1) * D + n], hi[q], lo[q]);
                }
                const int e = n * 8 + (c ^ (n & 7));
                g_Bimg[r * 1024 + e]       = make_uint4(hi[0], hi[1], hi[2], hi[3]);
                g_Bimg[r * 1024 + 512 + e] = make_uint4(lo[0], lo[1], lo[2], lo[3]);
            }
        }
    } else {
        // ---- bucket path: 4 samples per thread via int4 ----
        if (t < NUM_REL) s_count[t] = 0;
        __syncthreads();

        const int i4 = blockIdx.x * 256 + t;           // int4 index
        const int nv4 = B >> 2;                        // B assumed multiple of 4
        int rv[4] = {0, 0, 0, 0};
        int lp[4] = {0, 0, 0, 0};
        const bool valid = (i4 < nv4);
        if (valid) {
            const int4 v = reinterpret_cast<const int4*>(rels)[i4];
            rv[0] = v.x; rv[1] = v.y; rv[2] = v.z; rv[3] = v.w;
        }
        const unsigned am = __ballot_sync(0xffffffffu, valid);
        if (valid) {
            #pragma unroll
            for (int e = 0; e < 4; e++) {
                const unsigned mask   = __match_any_sync(am, rv[e]);
                const int      leader = __ffs(mask) - 1;
                const int      rank   = __popc(mask & ((1u << lane) - 1));
                int            base   = 0;
                if (lane == leader) base = atomicAdd(&s_count[rv[e]], __popc(mask));
                base = __shfl_sync(am, base, leader);
                lp[e] = base + rank;
            }
        }
        __syncthreads();
        if (t < NUM_REL) s_base[t] = atomicAdd(&g_counts[t], s_count[t]);
        __syncthreads();
        if (valid) {
            #pragma unroll
            for (int e = 0; e < 4; e++)
                g_idx[rv[e] * MAXB + s_base[rv[e]] + lp[e]] = i4 * 4 + e;
        }
    }

    // ---- common ticket + plan ----
    __threadfence();
    __syncthreads();
    if (t == 0) {
        int ticket = atomicAdd(&g_done, 1);
        s_last = (ticket == (int)gridDim.x - 1);
    }
    __syncthreads();
    if (s_last && t < 32) {
        int n = atomicAdd(&g_counts[t], 0);
        g_n[t] = n;
        g_counts[t] = 0;
        int ng = (n + GROUP - 1) / GROUP;
        int s = ng;
        #pragma unroll
        for (int o = 1; o < 32; o <<= 1) {
            int v = __shfl_up_sync(0xffffffffu, s, o);
            if (t >= o) s += v;
        }
        int start = s - ng;
        int total = __shfl_sync(0xffffffffu, s, 31);
        for (int g = 0; g < ng; g++) g_table[start + g] = t | (g << 8);
        for (int j = total + t; j < MAX_GROUPS; j += 32) g_table[j] = -1;
        if (t == 0) g_done = 0;
    }
}

// ---------------------------------------------------------------------------
// Kernel 2: score via mma.sync bf16 2-term split — EXACT round-12 kernel
// (proven 31.5us warm). Block = 128 samples of one relation, 4 warps;
// warp w owns m-rows [32w, 32w+32); single __syncthreads before mainloop.
// ---------------------------------------------------------------------------
__global__ void __launch_bounds__(THREADS, 4)
score_kernel(const float* __restrict__ e1g,
             const float* __restrict__ e2g,
             float* __restrict__ out)
{
    extern __shared__ __align__(1024) char smem[];
    const uint32_t sb = smem_u32(smem);
    int* s_idx = reinterpret_cast<int*>(smem + SM_IDX);

    const int item = g_table[blockIdx.x];
    if (item < 0) return;
    const int r    = item & 255;
    const int grp  = item >> 8;
    const int cnt0 = g_n[r] - grp * GROUP;
    const int cnt  = cnt0 < GROUP ? cnt0 : GROUP;
    const int* __restrict__ idx = g_idx + r * MAXB + grp * GROUP;

    const int t = threadIdx.x;
    const int b = idx[t < cnt ? t : cnt - 1];   // this thread's sample row
    s_idx[t] = b;

    // ---- B staging: copy pre-split swizzled image (1024 uint4 = 16 KB) ----
    {
        const uint4* src = g_Bimg + r * 1024;
        uint4* dst = reinterpret_cast<uint4*>(smem + SM_BHI);
        #pragma unroll
        for (int it = 0; it < 8; it++) dst[t + it * THREADS] = src[t + it * THREADS];
    }

    // ---- A staging: gather own e1 row, split, swizzled stores ----
    {
        const int m = t;
        const float4* p1 = reinterpret_cast<const float4*>(e1g) + b * (D / 4);
        #pragma unroll
        for (int c = 0; c < 8; c++) {              // chunk c: k = 8c..8c+7
            float4 f0 = p1[2 * c];
            float4 f1 = p1[2 * c + 1];
            uint32_t h0, l0, h1, l1, h2, l2, h3, l3;
            split2(f0.x, f0.y, h0, l0);
            split2(f0.z, f0.w, h1, l1);
            split2(f1.x, f1.y, h2, l2);
            split2(f1.z, f1.w, h3, l3);
            const uint32_t off = (uint32_t)(m * 128 + ((c ^ (m & 7)) << 4));
            *reinterpret_cast<uint4*>(smem + SM_AHI + off) = make_uint4(h0, h1, h2, h3);
            *reinterpret_cast<uint4*>(smem + SM_ALO + off) = make_uint4(l0, l1, l2, l3);
        }
    }
    __syncthreads();

    // ---- MMA mainloop ----
    const int lane = t & 31;
    const int w    = t >> 5;

    float acc[2][8][4];
    #pragma unroll
    for (int mt = 0; mt < 2; mt++)
        #pragma unroll
        for (int nt = 0; nt < 8; nt++)
            #pragma unroll
            for (int q = 0; q < 4; q++) acc[mt][nt][q] = 0.0f;

    #pragma unroll
    for (int ks = 0; ks < 4; ks++) {
        uint32_t ah[2][4], al[2][4];
        #pragma unroll
        for (int mt = 0; mt < 2; mt++) {
            const int row   = 32 * w + 16 * mt + (lane & 15);
            const int chunk = 2 * ks + (lane >> 4);
            const uint32_t off =
                (uint32_t)(row * 128 + ((chunk ^ (row & 7)) << 4));
            ldsm_x4(sb + SM_AHI + off, ah[mt][0], ah[mt][1], ah[mt][2], ah[mt][3]);
            ldsm_x4(sb + SM_ALO + off, al[mt][0], al[mt][1], al[mt][2], al[mt][3]);
        }
        uint32_t bh[8][2], bl[8][2];
        #pragma unroll
        for (int p = 0; p < 4; p++) {
            const int n     = 16 * p + ((lane >> 4) << 3) + (lane & 7);
            const int chunk = 2 * ks + ((lane >> 3) & 1);
            const uint32_t off =
                (uint32_t)(n * 128 + ((chunk ^ (n & 7)) << 4));
            ldsm_x4(sb + SM_BHI + off, bh[2 * p][0], bh[2 * p][1],
                                        bh[2 * p + 1][0], bh[2 * p + 1][1]);
            ldsm_x4(sb + SM_BLO + off, bl[2 * p][0], bl[2 * p][1],
                                        bl[2 * p + 1][0], bl[2 * p + 1][1]);
        }
        #pragma unroll
        for (int mt = 0; mt < 2; mt++)
            #pragma unroll
            for (int nt = 0; nt < 8; nt++) {
                mma_bf16(acc[mt][nt], ah[mt], bh[nt][0], bh[nt][1]);
                mma_bf16(acc[mt][nt], ah[mt], bl[nt][0], bl[nt][1]);
                mma_bf16(acc[mt][nt], al[mt], bh[nt][0], bh[nt][1]);
            }
    }

    // ---- epilogue: dot c-fragments with e2, quad-reduce, store ----
    {
        const int g  = lane >> 2;
        const int tg = lane & 3;
        #pragma unroll
        for (int mt = 0; mt < 2; mt++) {
            #pragma unroll
            for (int v = 0; v < 2; v++) {
                const int m  = 32 * w + 16 * mt + g + 8 * v;
                const int bm = s_idx[m];
                float p = 0.0f;
                #pragma unroll
                for (int nt = 0; nt < 8; nt++) {
                    const float2 u = *reinterpret_cast<const float2*>(
                        e2g + bm * D + nt * 8 + 2 * tg);
                    p += acc[mt][nt][2 * v]     * u.x;
                    p += acc[mt][nt][2 * v + 1] * u.y;
                }
                p += __shfl_xor_sync(0xffffffffu, p, 1);
                p += __shfl_xor_sync(0xffffffffu, p, 2);
                if (tg == 0 && m < cnt) out[bm] = p;
            }
        }
    }
}

// ---------------------------------------------------------------------------
// kernel_launch
// inputs: embeds1 [B*64] f32, embeds2 [B*64] f32, rels [B] i32,
//         rel_embeds [32*4096] f32 ; output [B] f32
// ---------------------------------------------------------------------------
extern "C" void kernel_launch(void* const* d_in, const int* in_sizes, int n_in,
                              void* d_out, int out_size) {
    const float* e1   = (const float*)d_in[0];
    const float* e2   = (const float*)d_in[1];
    const int*   rels = (const int*)d_in[2];
    const float* relw = (const float*)d_in[3];
    float* out = (float*)d_out;

    const int B = in_sizes[2];
    const int NB4 = (B / 4 + 255) / 256;   // int4-vectorized bucket blocks

    cudaFuncSetAttribute(score_kernel,
                         cudaFuncAttributeMaxDynamicSharedMemorySize, SMEM_TOTAL);

    bucket_kernel<<<NB4 + NUM_REL, 256>>>(rels, relw, B);
    score_kernel<<<MAX_GROUPS, THREADS, SMEM_TOTAL>>>(e1, e2, out);
}